// round 13
// baseline (speedup 1.0000x reference)
#include <cuda_runtime.h>
#include <math.h>

#define T_   8192
#define DIN  2048
#define D_   512
#define H_   512
#define H3_  1536
#define A_   18

#define CLN  16          // one cluster: 16 CTAs x 256 threads, 32 units/CTA

// ---------------- scratch (device globals: no allocation allowed) ----------
__device__ float g_z1[(size_t)T_ * D_];          // 16 MB
__device__ float g_z2[(size_t)T_ * D_];          // 16 MB
__device__ float g_X [(size_t)T_ * H3_];         // 48 MB
__device__ float g_seq[(size_t)T_ * H_];         // 16 MB

// ---------------- fp32 tiled GEMM: C = act(A[M,K] @ B[K,N] + bias) ---------
__global__ __launch_bounds__(256) void gemm_kernel(
    const float* __restrict__ A, const float* __restrict__ B,
    const float* __restrict__ bias, float* __restrict__ C,
    int M, int N, int K, int doRelu)
{
    __shared__ float As[16][64];
    __shared__ float Bs[16][64];
    const int tid = threadIdx.x;
    const int bm = blockIdx.y * 64;
    const int bn = blockIdx.x * 64;
    const int tx = tid & 15, ty = tid >> 4;

    const int aRow = tid >> 2;
    const int aK   = (tid & 3) << 2;
    const int bRow = tid >> 4;
    const int bCol = (tid & 15) << 2;

    const float* Aptr = A + (size_t)(bm + aRow) * K + aK;
    const float* Bptr = B + (size_t)bRow * N + bn + bCol;

    float acc[4][4];
#pragma unroll
    for (int i = 0; i < 4; i++)
#pragma unroll
        for (int j = 0; j < 4; j++) acc[i][j] = 0.f;

    for (int k0 = 0; k0 < K; k0 += 16) {
        float4 a4 = *(const float4*)(Aptr + k0);
        float4 b4 = *(const float4*)(Bptr + (size_t)k0 * N);
        As[aK + 0][aRow] = a4.x;
        As[aK + 1][aRow] = a4.y;
        As[aK + 2][aRow] = a4.z;
        As[aK + 3][aRow] = a4.w;
        *(float4*)&Bs[bRow][bCol] = b4;
        __syncthreads();
#pragma unroll
        for (int k = 0; k < 16; k++) {
            float4 av = *(const float4*)&As[k][ty << 2];
            float4 bv = *(const float4*)&Bs[k][tx << 2];
            float a_[4] = {av.x, av.y, av.z, av.w};
            float b_[4] = {bv.x, bv.y, bv.z, bv.w};
#pragma unroll
            for (int i = 0; i < 4; i++)
#pragma unroll
                for (int j = 0; j < 4; j++)
                    acc[i][j] = fmaf(a_[i], b_[j], acc[i][j]);
        }
        __syncthreads();
    }

#pragma unroll
    for (int i = 0; i < 4; i++) {
        int m = bm + (ty << 2) + i;
#pragma unroll
        for (int j = 0; j < 4; j++) {
            int n = bn + (tx << 2) + j;
            float v = acc[i][j] + bias[n];
            if (doRelu) v = fmaxf(v, 0.f);
            C[(size_t)m * N + n] = v;
        }
    }
}

// ---------------- GRU recurrence: 16-CTA cluster, decentralized PUSH --------
// ZERO intra-CTA barriers in the step loop. Every thread waits on the local
// mbarrier directly; each warp pushes its own 4 fresh h values (shfl-gathered,
// 16B) to all 16 CTAs the moment its gates are done, with one release-arrive
// per destination. mbarrier count = 128 (16 CTAs x 8 warps).
__global__ void __cluster_dims__(CLN, 1, 1) __launch_bounds__(256, 1)
recur_kernel(
    const float* __restrict__ Ug,    // [H, 3H] row-major
    const float* __restrict__ brec,  // [3H]  (bg row 1)
    const float* __restrict__ X,     // [T, 3H]
    float* __restrict__ seq,         // [T, H]
    float* __restrict__ hT_out,      // [H]
    const float* __restrict__ h0)    // [H]
{
    __shared__ __align__(16) float hloc[2][H_];     // incoming h, parity
    __shared__ __align__(8)  unsigned long long mb[2];

    const int tid  = threadIdx.x;
    const int lane = tid & 31;
    const int w    = tid >> 5;          // warp 0..7
    const int g    = lane >> 3;         // 8-lane group -> one unit
    const int s    = lane & 7;          // sub-lane in group
    unsigned rank;
    asm("mov.u32 %0, %%cluster_ctarank;" : "=r"(rank));
    const int ju = (int)rank * 32 + w * 4 + g;   // this group's global unit

    // ---- Ug slice in registers: wv[gate][i], k-pair p = s + 8*i -----------
    unsigned long long wv[3][32];
#pragma unroll
    for (int i = 0; i < 32; i++) {
        const int p = s + (i << 3);
        const float* r0 = Ug + (size_t)(2 * p) * H3_;
        const float* r1 = r0 + H3_;
#pragma unroll
        for (int c = 0; c < 3; c++) {
            float lo = r0[ju + c * H_], hi = r1[ju + c * H_];
            asm("mov.b64 %0, {%1, %2};" : "=l"(wv[c][i]) : "f"(lo), "f"(hi));
        }
    }
    float bz = 0.f, brr = 0.f, bh = 0.f, xz = 0.f, xr = 0.f, xh = 0.f;
    if (s == 0) {
        bz = brec[ju]; brr = brec[ju + H_]; bh = brec[ju + 2 * H_];
        xz = X[ju];    xr = X[ju + H_];     xh = X[ju + 2 * H_];
    }

    // ---- shared addresses --------------------------------------------------
    unsigned hloc_a, mb_a;
    asm("{ .reg .u64 t; cvta.to.shared.u64 t, %1; cvt.u32.u64 %0, t; }"
        : "=r"(hloc_a) : "l"((const void*)&hloc[0][0]));
    asm("{ .reg .u64 t; cvta.to.shared.u64 t, %1; cvt.u32.u64 %0, t; }"
        : "=r"(mb_a) : "l"((const void*)&mb[0]));

    // per-lane destination addresses (lanes 0..15 of EVERY warp -> CTA = lane)
    unsigned dstH = 0, dstM = 0;
    if (lane < 16) {
        asm("mapa.shared::cluster.u32 %0, %1, %2;"
            : "=r"(dstH) : "r"(hloc_a), "r"((unsigned)lane));
        asm("mapa.shared::cluster.u32 %0, %1, %2;"
            : "=r"(dstM) : "r"(mb_a), "r"((unsigned)lane));
    }
    // this warp's 16B slot inside each dest: rank*128 + w*16
    const unsigned slot = (unsigned)rank * 128u + (unsigned)(w << 4);

    // ---- init: 2 mbarriers, count 128 = 16 CTAs x 8 warps ------------------
    if (tid == 0) {
        asm volatile("mbarrier.init.shared.b64 [%0], 128;" :: "r"(mb_a) : "memory");
        asm volatile("mbarrier.init.shared.b64 [%0], 128;" :: "r"(mb_a + 8) : "memory");
    }
    __syncthreads();
    asm volatile("barrier.cluster.arrive.aligned;" ::: "memory");
    asm volatile("barrier.cluster.wait.aligned;"   ::: "memory");

    // ---- prologue: every warp pushes its 4 h_{-1} values (parity 0) --------
    {
        float hseed = (s == 0) ? h0[ju] : 0.f;
        float f0 = __shfl_sync(0xffffffffu, hseed, 0);
        float f1 = __shfl_sync(0xffffffffu, hseed, 8);
        float f2 = __shfl_sync(0xffffffffu, hseed, 16);
        float f3 = __shfl_sync(0xffffffffu, hseed, 24);
        unsigned long long v0, v1;
        asm("mov.b64 %0, {%1, %2};" : "=l"(v0) : "f"(f0), "f"(f1));
        asm("mov.b64 %0, {%1, %2};" : "=l"(v1) : "f"(f2), "f"(f3));
        if (lane < 16) {
            unsigned base = dstH + slot;                 // parity 0
            asm volatile("st.shared::cluster.u64 [%0], %1;" :: "r"(base), "l"(v0) : "memory");
            asm volatile("st.shared::cluster.u64 [%0], %1;" :: "r"(base + 8), "l"(v1) : "memory");
            asm volatile("mbarrier.arrive.release.cluster.shared::cluster.b64 _, [%0];"
                         :: "r"(dstM) : "memory");
        }
    }

    for (int t = 0; t < T_; t++) {
        const int par = t & 1;

        {   // ALL threads wait directly on the local mbarrier (no bar relay)
            unsigned ph = (unsigned)((t >> 1) & 1), done;
            do {
                asm volatile(
                    "{\n\t.reg .pred P;\n\t"
                    "mbarrier.try_wait.parity.acquire.cluster.shared::cta.b64 P, [%1], %2, 0x989680;\n\t"
                    "selp.b32 %0, 1, 0, P;\n\t}"
                    : "=r"(done) : "r"(mb_a + (unsigned)(par << 3)), "r"(ph) : "memory");
            } while (!done);
        }

        // prefetch next step's X row (full step of cover)
        float nxz = 0.f, nxr = 0.f, nxh = 0.f;
        if (s == 0 && t + 1 < T_) {
            const float* xp = X + (size_t)(t + 1) * H3_;
            nxz = __ldcs(xp + ju); nxr = __ldcs(xp + ju + H_); nxh = __ldcs(xp + ju + 2 * H_);
        }

        // dots from LOCAL smem (h was pushed to us)
        const unsigned long long* hl = (const unsigned long long*)hloc[par];
        unsigned long long a0e = 0ull, a1e = 0ull, a2e = 0ull;
        unsigned long long a0o = 0ull, a1o = 0ull, a2o = 0ull;
#pragma unroll
        for (int i = 0; i < 32; i += 2) {
            unsigned long long h0v = hl[s + (i << 3)];
            unsigned long long h1v = hl[s + ((i + 1) << 3)];
            asm("fma.rn.f32x2 %0, %1, %2, %3;" : "=l"(a0e) : "l"(h0v), "l"(wv[0][i]), "l"(a0e));
            asm("fma.rn.f32x2 %0, %1, %2, %3;" : "=l"(a1e) : "l"(h0v), "l"(wv[1][i]), "l"(a1e));
            asm("fma.rn.f32x2 %0, %1, %2, %3;" : "=l"(a2e) : "l"(h0v), "l"(wv[2][i]), "l"(a2e));
            asm("fma.rn.f32x2 %0, %1, %2, %3;" : "=l"(a0o) : "l"(h1v), "l"(wv[0][i + 1]), "l"(a0o));
            asm("fma.rn.f32x2 %0, %1, %2, %3;" : "=l"(a1o) : "l"(h1v), "l"(wv[1][i + 1]), "l"(a1o));
            asm("fma.rn.f32x2 %0, %1, %2, %3;" : "=l"(a2o) : "l"(h1v), "l"(wv[2][i + 1]), "l"(a2o));
        }
        float s0, s1, s2;
        {
            float lo, hi, lo2, hi2;
            asm("mov.b64 {%0, %1}, %2;" : "=f"(lo), "=f"(hi) : "l"(a0e));
            asm("mov.b64 {%0, %1}, %2;" : "=f"(lo2), "=f"(hi2) : "l"(a0o));
            s0 = (lo + hi) + (lo2 + hi2);
            asm("mov.b64 {%0, %1}, %2;" : "=f"(lo), "=f"(hi) : "l"(a1e));
            asm("mov.b64 {%0, %1}, %2;" : "=f"(lo2), "=f"(hi2) : "l"(a1o));
            s1 = (lo + hi) + (lo2 + hi2);
            asm("mov.b64 {%0, %1}, %2;" : "=f"(lo), "=f"(hi) : "l"(a2e));
            asm("mov.b64 {%0, %1}, %2;" : "=f"(lo2), "=f"(hi2) : "l"(a2o));
            s2 = (lo + hi) + (lo2 + hi2);
        }
#pragma unroll
        for (int off = 4; off; off >>= 1) {
            s0 += __shfl_xor_sync(0xffffffffu, s0, off);
            s1 += __shfl_xor_sync(0xffffffffu, s1, off);
            s2 += __shfl_xor_sync(0xffffffffu, s2, off);
        }

        float hn = 0.f;
        if (s == 0) {
            float zt = __fdividef(1.f, 1.f + __expf(-(xz + s0 + bz)));
            float rt = __fdividef(1.f, 1.f + __expf(-(xr + s1 + brr)));
            float hh = __fdividef(1.f, 1.f + __expf(-(xh + rt * (s2 + bh))));
            float hp = hloc[par][ju];
            hn = fmaf(zt, hp - hh, hh);         // zt*hp + (1-zt)*hh
        }

        // warp-local gather of this warp's 4 new h values
        float f0 = __shfl_sync(0xffffffffu, hn, 0);
        float f1 = __shfl_sync(0xffffffffu, hn, 8);
        float f2 = __shfl_sync(0xffffffffu, hn, 16);
        float f3 = __shfl_sync(0xffffffffu, hn, 24);
        unsigned long long v0, v1;
        asm("mov.b64 %0, {%1, %2};" : "=l"(v0) : "f"(f0), "f"(f1));
        asm("mov.b64 %0, {%1, %2};" : "=l"(v1) : "f"(f2), "f"(f3));

        // push this warp's slice to all 16 CTAs (lanes 0..15, 16B each + arrive)
        if (t + 1 < T_ && lane < 16) {
            const unsigned par2 = (unsigned)((t + 1) & 1);
            unsigned base = dstH + (par2 << 11) + slot;
            asm volatile("st.shared::cluster.u64 [%0], %1;" :: "r"(base), "l"(v0) : "memory");
            asm volatile("st.shared::cluster.u64 [%0], %1;" :: "r"(base + 8), "l"(v1) : "memory");
            asm volatile("mbarrier.arrive.release.cluster.shared::cluster.b64 _, [%0];"
                         :: "r"(dstM + (par2 << 3)) : "memory");
        }

        // bookkeeping off the critical path
        if (s == 0) {
            seq[(size_t)t * H_ + ju] = hn;
            if (t == T_ - 1) hT_out[ju] = hn;
            xz = nxz; xr = nxr; xh = nxh;
        }
    }

    asm volatile("barrier.cluster.arrive.aligned;" ::: "memory");
    asm volatile("barrier.cluster.wait.aligned;"   ::: "memory");
}

// ---------------- heads: softmax policy (18) + value, one warp per row -----
__global__ __launch_bounds__(256) void head_kernel(
    const float* __restrict__ seq, const float* __restrict__ Wp,
    const float* __restrict__ bp,  const float* __restrict__ Wv,
    const float* __restrict__ bv,  float* __restrict__ out)
{
    int row  = blockIdx.x * (blockDim.x >> 5) + (threadIdx.x >> 5);
    int lane = threadIdx.x & 31;
    if (row >= T_) return;
    const float* h = seq + (size_t)row * H_;

    const float* wcol = (lane < 18) ? (Wp + lane) : Wv;
    const int stride  = (lane < 18) ? A_ : 1;
    float acc = 0.f;
    if (lane < 19) {
#pragma unroll 8
        for (int k = 0; k < H_; k++)
            acc = fmaf(__ldg(h + k), __ldg(wcol + k * stride), acc);
    }

    const float NEG_INF = __int_as_float(0xff800000);
    float logit = (lane < 18) ? acc + bp[lane] : NEG_INF;
    float m = logit;
#pragma unroll
    for (int off = 16; off; off >>= 1)
        m = fmaxf(m, __shfl_xor_sync(0xffffffffu, m, off));
    float e = (lane < 18) ? __expf(logit - m) : 0.f;
    float s = e;
#pragma unroll
    for (int off = 16; off; off >>= 1)
        s += __shfl_xor_sync(0xffffffffu, s, off);

    if (lane < 18)  out[(size_t)row * A_ + lane] = e / s;
    if (lane == 18) out[(size_t)T_ * A_ + row]   = acc + bv[0];
}

// ---------------- launch --------------------------------------------------
extern "C" void kernel_launch(void* const* d_in, const int* in_sizes, int n_in,
                              void* d_out, int out_size)
{
    (void)in_sizes; (void)n_in; (void)out_size;
    const float* x  = (const float*)d_in[0];
    const float* h0 = (const float*)d_in[1];
    const float* W1 = (const float*)d_in[2];
    const float* b1 = (const float*)d_in[3];
    const float* W2 = (const float*)d_in[4];
    const float* b2 = (const float*)d_in[5];
    const float* Wg = (const float*)d_in[6];
    const float* Ug = (const float*)d_in[7];
    const float* bg = (const float*)d_in[8];
    const float* Wp = (const float*)d_in[9];
    const float* bp = (const float*)d_in[10];
    const float* Wv = (const float*)d_in[11];
    const float* bv = (const float*)d_in[12];
    float* out = (float*)d_out;

    float *z1p, *z2p, *Xp, *seqp;
    cudaGetSymbolAddress((void**)&z1p,  g_z1);
    cudaGetSymbolAddress((void**)&z2p,  g_z2);
    cudaGetSymbolAddress((void**)&Xp,   g_X);
    cudaGetSymbolAddress((void**)&seqp, g_seq);

    static int attrSet = 0;
    if (!attrSet) {
        cudaFuncSetAttribute(recur_kernel,
                             cudaFuncAttributeNonPortableClusterSizeAllowed, 1);
        attrSet = 1;
    }

    gemm_kernel<<<dim3(D_ / 64,  T_ / 64), 256>>>(x,   W1, b1, z1p, T_, D_,  DIN, 1);
    gemm_kernel<<<dim3(D_ / 64,  T_ / 64), 256>>>(z1p, W2, b2, z2p, T_, D_,  D_,  1);
    gemm_kernel<<<dim3(H3_ / 64, T_ / 64), 256>>>(z2p, Wg, bg, Xp,  T_, H3_, D_,  0);
    recur_kernel<<<CLN, 256>>>(Ug, bg + H3_, Xp, seqp,
                               out + (size_t)T_ * A_ + T_, h0);
    head_kernel<<<T_ / 8, 256>>>(seqp, Wp, bp, Wv, bv, out);
}

// round 14
// speedup vs baseline: 1.2583x; 1.2583x over previous
#include <cuda_runtime.h>
#include <math.h>

#define T_   8192
#define DIN  2048
#define D_   512
#define H_   512
#define H3_  1536
#define A_   18

#define CLN  16          // one cluster: 16 CTAs x 256 threads, 32 units/CTA

// ---------------- scratch (device globals: no allocation allowed) ----------
__device__ float g_z1[(size_t)T_ * D_];          // 16 MB
__device__ float g_z2[(size_t)T_ * D_];          // 16 MB
__device__ float g_X [(size_t)T_ * H3_];         // 48 MB
__device__ float g_seq[(size_t)T_ * H_];         // 16 MB

// ---------------- fp32 tiled GEMM: C = act(A[M,K] @ B[K,N] + bias) ---------
__global__ __launch_bounds__(256) void gemm_kernel(
    const float* __restrict__ A, const float* __restrict__ B,
    const float* __restrict__ bias, float* __restrict__ C,
    int M, int N, int K, int doRelu)
{
    __shared__ float As[16][64];
    __shared__ float Bs[16][64];
    const int tid = threadIdx.x;
    const int bm = blockIdx.y * 64;
    const int bn = blockIdx.x * 64;
    const int tx = tid & 15, ty = tid >> 4;

    const int aRow = tid >> 2;
    const int aK   = (tid & 3) << 2;
    const int bRow = tid >> 4;
    const int bCol = (tid & 15) << 2;

    const float* Aptr = A + (size_t)(bm + aRow) * K + aK;
    const float* Bptr = B + (size_t)bRow * N + bn + bCol;

    float acc[4][4];
#pragma unroll
    for (int i = 0; i < 4; i++)
#pragma unroll
        for (int j = 0; j < 4; j++) acc[i][j] = 0.f;

    for (int k0 = 0; k0 < K; k0 += 16) {
        float4 a4 = *(const float4*)(Aptr + k0);
        float4 b4 = *(const float4*)(Bptr + (size_t)k0 * N);
        As[aK + 0][aRow] = a4.x;
        As[aK + 1][aRow] = a4.y;
        As[aK + 2][aRow] = a4.z;
        As[aK + 3][aRow] = a4.w;
        *(float4*)&Bs[bRow][bCol] = b4;
        __syncthreads();
#pragma unroll
        for (int k = 0; k < 16; k++) {
            float4 av = *(const float4*)&As[k][ty << 2];
            float4 bv = *(const float4*)&Bs[k][tx << 2];
            float a_[4] = {av.x, av.y, av.z, av.w};
            float b_[4] = {bv.x, bv.y, bv.z, bv.w};
#pragma unroll
            for (int i = 0; i < 4; i++)
#pragma unroll
                for (int j = 0; j < 4; j++)
                    acc[i][j] = fmaf(a_[i], b_[j], acc[i][j]);
        }
        __syncthreads();
    }

#pragma unroll
    for (int i = 0; i < 4; i++) {
        int m = bm + (ty << 2) + i;
#pragma unroll
        for (int j = 0; j < 4; j++) {
            int n = bn + (tx << 2) + j;
            float v = acc[i][j] + bias[n];
            if (doRelu) v = fmaxf(v, 0.f);
            C[(size_t)m * N + n] = v;
        }
    }
}

// ---------------- GRU recurrence: 16-CTA cluster, hybrid PUSH ---------------
// Per-warp direct remote data stores (one 16B st.shared::cluster.v2.u64 per
// lane<16, issued the moment the warp's gates finish -> stores land inside the
// skew window), then ONE CTA barrier orders them, then warp-0 lanes issue the
// 16 release-arrives (arrive fan-in stays at 16/phase -- R13 showed 128 is
// the regression). Consumer side identical to R11 (warp-0 wait + bar relay).
__global__ void __cluster_dims__(CLN, 1, 1) __launch_bounds__(256, 1)
recur_kernel(
    const float* __restrict__ Ug,    // [H, 3H] row-major
    const float* __restrict__ brec,  // [3H]  (bg row 1)
    const float* __restrict__ X,     // [T, 3H]
    float* __restrict__ seq,         // [T, H]
    float* __restrict__ hT_out,      // [H]
    const float* __restrict__ h0)    // [H]
{
    __shared__ __align__(16) float hloc[2][H_];     // incoming h, parity
    __shared__ __align__(8)  unsigned long long mb[2];

    const int tid  = threadIdx.x;
    const int lane = tid & 31;
    const int w    = tid >> 5;          // warp 0..7
    const int g    = lane >> 3;         // 8-lane group -> one unit
    const int s    = lane & 7;          // sub-lane in group
    unsigned rank;
    asm("mov.u32 %0, %%cluster_ctarank;" : "=r"(rank));
    const int ju = (int)rank * 32 + w * 4 + g;   // this group's global unit

    // ---- Ug slice in registers: wv[gate][i], k-pair p = s + 8*i -----------
    unsigned long long wv[3][32];
#pragma unroll
    for (int i = 0; i < 32; i++) {
        const int p = s + (i << 3);
        const float* r0 = Ug + (size_t)(2 * p) * H3_;
        const float* r1 = r0 + H3_;
#pragma unroll
        for (int c = 0; c < 3; c++) {
            float lo = r0[ju + c * H_], hi = r1[ju + c * H_];
            asm("mov.b64 %0, {%1, %2};" : "=l"(wv[c][i]) : "f"(lo), "f"(hi));
        }
    }
    float bz = 0.f, brr = 0.f, bh = 0.f, xz = 0.f, xr = 0.f, xh = 0.f;
    if (s == 0) {
        bz = brec[ju]; brr = brec[ju + H_]; bh = brec[ju + 2 * H_];
        xz = X[ju];    xr = X[ju + H_];     xh = X[ju + 2 * H_];
    }

    // ---- shared addresses --------------------------------------------------
    unsigned hloc_a, mb_a;
    asm("{ .reg .u64 t; cvta.to.shared.u64 t, %1; cvt.u32.u64 %0, t; }"
        : "=r"(hloc_a) : "l"((const void*)&hloc[0][0]));
    asm("{ .reg .u64 t; cvta.to.shared.u64 t, %1; cvt.u32.u64 %0, t; }"
        : "=r"(mb_a) : "l"((const void*)&mb[0]));

    // per-lane destination addresses (lanes 0..15 of EVERY warp -> CTA = lane)
    unsigned dstH = 0, dstM = 0;
    if (lane < 16) {
        asm("mapa.shared::cluster.u32 %0, %1, %2;"
            : "=r"(dstH) : "r"(hloc_a), "r"((unsigned)lane));
        asm("mapa.shared::cluster.u32 %0, %1, %2;"
            : "=r"(dstM) : "r"(mb_a), "r"((unsigned)lane));
    }
    // this warp's 16B slot inside each dest: rank*128 + w*16
    const unsigned slot = (unsigned)rank * 128u + (unsigned)(w << 4);

    // ---- init: 2 mbarriers, count 16 (one release-arrive per source CTA) ---
    if (tid == 0) {
        asm volatile("mbarrier.init.shared.b64 [%0], 16;" :: "r"(mb_a) : "memory");
        asm volatile("mbarrier.init.shared.b64 [%0], 16;" :: "r"(mb_a + 8) : "memory");
    }
    __syncthreads();
    asm volatile("barrier.cluster.arrive.aligned;" ::: "memory");
    asm volatile("barrier.cluster.wait.aligned;"   ::: "memory");

    // ---- prologue: push h_{-1} (parity 0): per-warp stores, bar, 16 arrives -
    {
        float hseed = (s == 0) ? h0[ju] : 0.f;
        float f0 = __shfl_sync(0xffffffffu, hseed, 0);
        float f1 = __shfl_sync(0xffffffffu, hseed, 8);
        float f2 = __shfl_sync(0xffffffffu, hseed, 16);
        float f3 = __shfl_sync(0xffffffffu, hseed, 24);
        unsigned long long v0, v1;
        asm("mov.b64 %0, {%1, %2};" : "=l"(v0) : "f"(f0), "f"(f1));
        asm("mov.b64 %0, {%1, %2};" : "=l"(v1) : "f"(f2), "f"(f3));
        if (lane < 16)
            asm volatile("st.shared::cluster.v2.u64 [%0], {%1, %2};"
                         :: "r"(dstH + slot), "l"(v0), "l"(v1) : "memory");
        __syncthreads();
        if (tid < 16)
            asm volatile("mbarrier.arrive.release.cluster.shared::cluster.b64 _, [%0];"
                         :: "r"(dstM) : "memory");
    }

    for (int t = 0; t < T_; t++) {
        const int par = t & 1;

        if (w == 0) {   // consumer wait: warp 0 only (proven R11 pattern)
            unsigned ph = (unsigned)((t >> 1) & 1), done;
            do {
                asm volatile(
                    "{\n\t.reg .pred P;\n\t"
                    "mbarrier.try_wait.parity.acquire.cluster.shared::cta.b64 P, [%1], %2, 0x989680;\n\t"
                    "selp.b32 %0, 1, 0, P;\n\t}"
                    : "=r"(done) : "r"(mb_a + (unsigned)(par << 3)), "r"(ph) : "memory");
            } while (!done);
        }
        __syncthreads();                               // bar A: release CTA

        // prefetch next step's X row (full step of cover)
        float nxz = 0.f, nxr = 0.f, nxh = 0.f;
        if (s == 0 && t + 1 < T_) {
            const float* xp = X + (size_t)(t + 1) * H3_;
            nxz = __ldcs(xp + ju); nxr = __ldcs(xp + ju + H_); nxh = __ldcs(xp + ju + 2 * H_);
        }

        // dots from LOCAL smem (h was pushed to us)
        const unsigned long long* hl = (const unsigned long long*)hloc[par];
        unsigned long long a0e = 0ull, a1e = 0ull, a2e = 0ull;
        unsigned long long a0o = 0ull, a1o = 0ull, a2o = 0ull;
#pragma unroll
        for (int i = 0; i < 32; i += 2) {
            unsigned long long h0v = hl[s + (i << 3)];
            unsigned long long h1v = hl[s + ((i + 1) << 3)];
            asm("fma.rn.f32x2 %0, %1, %2, %3;" : "=l"(a0e) : "l"(h0v), "l"(wv[0][i]), "l"(a0e));
            asm("fma.rn.f32x2 %0, %1, %2, %3;" : "=l"(a1e) : "l"(h0v), "l"(wv[1][i]), "l"(a1e));
            asm("fma.rn.f32x2 %0, %1, %2, %3;" : "=l"(a2e) : "l"(h0v), "l"(wv[2][i]), "l"(a2e));
            asm("fma.rn.f32x2 %0, %1, %2, %3;" : "=l"(a0o) : "l"(h1v), "l"(wv[0][i + 1]), "l"(a0o));
            asm("fma.rn.f32x2 %0, %1, %2, %3;" : "=l"(a1o) : "l"(h1v), "l"(wv[1][i + 1]), "l"(a1o));
            asm("fma.rn.f32x2 %0, %1, %2, %3;" : "=l"(a2o) : "l"(h1v), "l"(wv[2][i + 1]), "l"(a2o));
        }
        float s0, s1, s2;
        {
            float lo, hi, lo2, hi2;
            asm("mov.b64 {%0, %1}, %2;" : "=f"(lo), "=f"(hi) : "l"(a0e));
            asm("mov.b64 {%0, %1}, %2;" : "=f"(lo2), "=f"(hi2) : "l"(a0o));
            s0 = (lo + hi) + (lo2 + hi2);
            asm("mov.b64 {%0, %1}, %2;" : "=f"(lo), "=f"(hi) : "l"(a1e));
            asm("mov.b64 {%0, %1}, %2;" : "=f"(lo2), "=f"(hi2) : "l"(a1o));
            s1 = (lo + hi) + (lo2 + hi2);
            asm("mov.b64 {%0, %1}, %2;" : "=f"(lo), "=f"(hi) : "l"(a2e));
            asm("mov.b64 {%0, %1}, %2;" : "=f"(lo2), "=f"(hi2) : "l"(a2o));
            s2 = (lo + hi) + (lo2 + hi2);
        }
#pragma unroll
        for (int off = 4; off; off >>= 1) {
            s0 += __shfl_xor_sync(0xffffffffu, s0, off);
            s1 += __shfl_xor_sync(0xffffffffu, s1, off);
            s2 += __shfl_xor_sync(0xffffffffu, s2, off);
        }

        float hn = 0.f;
        if (s == 0) {
            float zt = __fdividef(1.f, 1.f + __expf(-(xz + s0 + bz)));
            float rt = __fdividef(1.f, 1.f + __expf(-(xr + s1 + brr)));
            float hh = __fdividef(1.f, 1.f + __expf(-(xh + rt * (s2 + bh))));
            float hp = hloc[par][ju];
            hn = fmaf(zt, hp - hh, hh);         // zt*hp + (1-zt)*hh
        }

        // per-warp DIRECT remote data stores (inside the skew window)
        {
            float f0 = __shfl_sync(0xffffffffu, hn, 0);
            float f1 = __shfl_sync(0xffffffffu, hn, 8);
            float f2 = __shfl_sync(0xffffffffu, hn, 16);
            float f3 = __shfl_sync(0xffffffffu, hn, 24);
            unsigned long long v0, v1;
            asm("mov.b64 %0, {%1, %2};" : "=l"(v0) : "f"(f0), "f"(f1));
            asm("mov.b64 %0, {%1, %2};" : "=l"(v1) : "f"(f2), "f"(f3));
            if (t + 1 < T_ && lane < 16) {
                const unsigned par2 = (unsigned)((t + 1) & 1);
                asm volatile("st.shared::cluster.v2.u64 [%0], {%1, %2};"
                             :: "r"(dstH + (par2 << 11) + slot), "l"(v0), "l"(v1)
                             : "memory");
            }
        }
        __syncthreads();                               // bar B: order all stores

        if (t + 1 < T_ && tid < 16)                    // 16 release-arrives only
            asm volatile("mbarrier.arrive.release.cluster.shared::cluster.b64 _, [%0];"
                         :: "r"(dstM + (unsigned)(((t + 1) & 1) << 3)) : "memory");

        // bookkeeping off the critical path
        if (s == 0) {
            seq[(size_t)t * H_ + ju] = hn;
            if (t == T_ - 1) hT_out[ju] = hn;
            xz = nxz; xr = nxr; xh = nxh;
        }
    }

    asm volatile("barrier.cluster.arrive.aligned;" ::: "memory");
    asm volatile("barrier.cluster.wait.aligned;"   ::: "memory");
}

// ---------------- heads: softmax policy (18) + value, one warp per row -----
__global__ __launch_bounds__(256) void head_kernel(
    const float* __restrict__ seq, const float* __restrict__ Wp,
    const float* __restrict__ bp,  const float* __restrict__ Wv,
    const float* __restrict__ bv,  float* __restrict__ out)
{
    int row  = blockIdx.x * (blockDim.x >> 5) + (threadIdx.x >> 5);
    int lane = threadIdx.x & 31;
    if (row >= T_) return;
    const float* h = seq + (size_t)row * H_;

    const float* wcol = (lane < 18) ? (Wp + lane) : Wv;
    const int stride  = (lane < 18) ? A_ : 1;
    float acc = 0.f;
    if (lane < 19) {
#pragma unroll 8
        for (int k = 0; k < H_; k++)
            acc = fmaf(__ldg(h + k), __ldg(wcol + k * stride), acc);
    }

    const float NEG_INF = __int_as_float(0xff800000);
    float logit = (lane < 18) ? acc + bp[lane] : NEG_INF;
    float m = logit;
#pragma unroll
    for (int off = 16; off; off >>= 1)
        m = fmaxf(m, __shfl_xor_sync(0xffffffffu, m, off));
    float e = (lane < 18) ? __expf(logit - m) : 0.f;
    float s = e;
#pragma unroll
    for (int off = 16; off; off >>= 1)
        s += __shfl_xor_sync(0xffffffffu, s, off);

    if (lane < 18)  out[(size_t)row * A_ + lane] = e / s;
    if (lane == 18) out[(size_t)T_ * A_ + row]   = acc + bv[0];
}

// ---------------- launch --------------------------------------------------
extern "C" void kernel_launch(void* const* d_in, const int* in_sizes, int n_in,
                              void* d_out, int out_size)
{
    (void)in_sizes; (void)n_in; (void)out_size;
    const float* x  = (const float*)d_in[0];
    const float* h0 = (const float*)d_in[1];
    const float* W1 = (const float*)d_in[2];
    const float* b1 = (const float*)d_in[3];
    const float* W2 = (const float*)d_in[4];
    const float* b2 = (const float*)d_in[5];
    const float* Wg = (const float*)d_in[6];
    const float* Ug = (const float*)d_in[7];
    const float* bg = (const float*)d_in[8];
    const float* Wp = (const float*)d_in[9];
    const float* bp = (const float*)d_in[10];
    const float* Wv = (const float*)d_in[11];
    const float* bv = (const float*)d_in[12];
    float* out = (float*)d_out;

    float *z1p, *z2p, *Xp, *seqp;
    cudaGetSymbolAddress((void**)&z1p,  g_z1);
    cudaGetSymbolAddress((void**)&z2p,  g_z2);
    cudaGetSymbolAddress((void**)&Xp,   g_X);
    cudaGetSymbolAddress((void**)&seqp, g_seq);

    static int attrSet = 0;
    if (!attrSet) {
        cudaFuncSetAttribute(recur_kernel,
                             cudaFuncAttributeNonPortableClusterSizeAllowed, 1);
        attrSet = 1;
    }

    gemm_kernel<<<dim3(D_ / 64,  T_ / 64), 256>>>(x,   W1, b1, z1p, T_, D_,  DIN, 1);
    gemm_kernel<<<dim3(D_ / 64,  T_ / 64), 256>>>(z1p, W2, b2, z2p, T_, D_,  D_,  1);
    gemm_kernel<<<dim3(H3_ / 64, T_ / 64), 256>>>(z2p, Wg, bg, Xp,  T_, H3_, D_,  0);
    recur_kernel<<<CLN, 256>>>(Ug, bg + H3_, Xp, seqp,
                               out + (size_t)T_ * A_ + T_, h0);
    head_kernel<<<T_ / 8, 256>>>(seqp, Wp, bp, Wv, bv, out);
}